// round 1
// baseline (speedup 1.0000x reference)
#include <cuda_runtime.h>
#include <math.h>

#define N_NODES 8192
#define F_IN    512
#define HID     128
#define NCLS    16
#define CAP     160

// ---------------- static scratch (no allocations allowed) ----------------
__device__ float g_dinv[N_NODES];
__device__ int   g_cnt [N_NODES];
__device__ int   g_cols[(size_t)N_NODES * CAP];
__device__ float g_vals[(size_t)N_NODES * CAP];
__device__ float g_h1 [(size_t)N_NODES * HID];
__device__ float g_b1a[(size_t)N_NODES * HID];
__device__ float g_b1b[(size_t)N_NODES * HID];
__device__ float g_h2 [(size_t)N_NODES * NCLS];
__device__ float g_c2a[(size_t)N_NODES * NCLS];
__device__ float g_c2b[(size_t)N_NODES * NCLS];

__device__ __constant__ float C_RES  = (float)(1.0 / 1.8);   // 1/(1+alpha)
__device__ __constant__ float C_PROP = (float)(0.8 / 1.8);   // alpha/(1+alpha)

// ---------------- 1: degrees -> dinv ----------------
__global__ void deg_kernel(const float* __restrict__ adj) {
    int row = blockIdx.x;
    const float4* p = (const float4*)(adj + (size_t)row * N_NODES);
    float s = 0.f;
    for (int j = threadIdx.x; j < N_NODES / 4; j += blockDim.x) {
        float4 v = p[j];
        s += v.x + v.y + v.z + v.w;
    }
    __shared__ float red[256];
    red[threadIdx.x] = s;
    __syncthreads();
    for (int o = 128; o > 0; o >>= 1) {
        if (threadIdx.x < o) red[threadIdx.x] += red[threadIdx.x + o];
        __syncthreads();
    }
    if (threadIdx.x == 0) {
        float d = red[0] + 1.0f;                 // self-loop
        g_dinv[row] = rsqrtf(fmaxf(d, 1e-12f));
    }
}

// ---------------- 2: build ELL (one warp per row, ballot compaction) ----------------
__global__ void build_kernel(const float* __restrict__ adj) {
    int warp = (blockIdx.x * blockDim.x + threadIdx.x) >> 5;
    int lane = threadIdx.x & 31;
    if (warp >= N_NODES) return;
    const float di = g_dinv[warp];
    const float* rowp = adj + (size_t)warp * N_NODES;
    size_t base = (size_t)warp * CAP;
    int cnt = 0;
    for (int j0 = 0; j0 < N_NODES; j0 += 32) {
        int j = j0 + lane;
        float v = rowp[j];
        float b = v + ((j == warp) ? 1.0f : 0.0f);   // A + I entry
        bool pred = (b != 0.0f);
        unsigned mask = __ballot_sync(0xffffffffu, pred);
        if (pred) {
            int idx = cnt + __popc(mask & ((1u << lane) - 1u));
            if (idx < CAP) {
                g_cols[base + idx] = j;
                g_vals[base + idx] = b * di * g_dinv[j];
            }
        }
        cnt += __popc(mask);
    }
    if (lane == 0) g_cnt[warp] = (cnt < CAP) ? cnt : CAP;
}

// ---------------- 3: SGEMM  C[8192,128] = A[8192,512] @ B[512,128] ----------------
__global__ void gemm1_kernel(const float* __restrict__ A, const float* __restrict__ B,
                             float* __restrict__ C) {
    const int BM = 64, BN = 64, BK = 16;
    __shared__ float As[BK][BM];
    __shared__ float Bs[BK][BN];
    int m0 = blockIdx.x * BM;
    int n0 = blockIdx.y * BN;
    int t  = threadIdx.x;
    int tx = t & 15, ty = t >> 4;
    float acc[4][4] = {};
    for (int k0 = 0; k0 < F_IN; k0 += BK) {
        {   // load A tile (transposed into smem)
            int r = t >> 2, c4 = t & 3;
            float4 a = *(const float4*)(A + (size_t)(m0 + r) * F_IN + k0 + c4 * 4);
            As[c4 * 4 + 0][r] = a.x; As[c4 * 4 + 1][r] = a.y;
            As[c4 * 4 + 2][r] = a.z; As[c4 * 4 + 3][r] = a.w;
        }
        {   // load B tile
            int kr = t >> 4, c4 = t & 15;
            float4 b = *(const float4*)(B + (size_t)(k0 + kr) * HID + n0 + c4 * 4);
            Bs[kr][c4 * 4 + 0] = b.x; Bs[kr][c4 * 4 + 1] = b.y;
            Bs[kr][c4 * 4 + 2] = b.z; Bs[kr][c4 * 4 + 3] = b.w;
        }
        __syncthreads();
#pragma unroll
        for (int k = 0; k < BK; k++) {
            float av[4], bv[4];
#pragma unroll
            for (int i = 0; i < 4; i++) av[i] = As[k][ty * 4 + i];
#pragma unroll
            for (int j = 0; j < 4; j++) bv[j] = Bs[k][tx * 4 + j];
#pragma unroll
            for (int i = 0; i < 4; i++)
#pragma unroll
                for (int j = 0; j < 4; j++)
                    acc[i][j] = fmaf(av[i], bv[j], acc[i][j]);
        }
        __syncthreads();
    }
#pragma unroll
    for (int i = 0; i < 4; i++)
#pragma unroll
        for (int j = 0; j < 4; j++)
            C[(size_t)(m0 + ty * 4 + i) * HID + n0 + tx * 4 + j] = acc[i][j];
}

// ---------------- 4: SpMM diffusion step, F=128 (float4, 32 lanes/row, 8 rows/block) ----
template <bool FINAL>
__global__ void spmm_h(const float* __restrict__ in, const float* __restrict__ h,
                       float* __restrict__ out, const float* __restrict__ bias) {
    int warp = threadIdx.x >> 5;
    int lane = threadIdx.x & 31;
    int row  = blockIdx.x * 8 + warp;
    size_t base = (size_t)row * CAP;
    int cnt = g_cnt[row];
    const float4* inv = (const float4*)in;
    float4 acc = make_float4(0.f, 0.f, 0.f, 0.f);
#pragma unroll 4
    for (int e = 0; e < cnt; e++) {
        int   c = __ldg(&g_cols[base + e]);
        float v = __ldg(&g_vals[base + e]);
        float4 o = __ldg(&inv[(size_t)c * (HID / 4) + lane]);
        acc.x = fmaf(v, o.x, acc.x);
        acc.y = fmaf(v, o.y, acc.y);
        acc.z = fmaf(v, o.z, acc.z);
        acc.w = fmaf(v, o.w, acc.w);
    }
    float4 hh = ((const float4*)h)[(size_t)row * (HID / 4) + lane];
    float4 r;
    r.x = C_PROP * acc.x + C_RES * hh.x;
    r.y = C_PROP * acc.y + C_RES * hh.y;
    r.z = C_PROP * acc.z + C_RES * hh.z;
    r.w = C_PROP * acc.w + C_RES * hh.w;
    if (FINAL) {
        float4 b = ((const float4*)bias)[lane];
        r.x = fmaxf(r.x + b.x, 0.f);
        r.y = fmaxf(r.y + b.y, 0.f);
        r.z = fmaxf(r.z + b.z, 0.f);
        r.w = fmaxf(r.w + b.w, 0.f);
    }
    ((float4*)out)[(size_t)row * (HID / 4) + lane] = r;
}

// ---------------- 5: small GEMM  h2[8192,16] = H[8192,128] @ W2[128,16] ----------------
__global__ void gemm2_kernel(const float* __restrict__ Hm, const float* __restrict__ W2) {
    __shared__ float sW[128 * 16];
    __shared__ float sH[16 * 128];
    int t = threadIdx.x;
    int row0 = blockIdx.x * 16;
    for (int i = t; i < 128 * 16; i += 256) sW[i] = W2[i];
    for (int i = t; i < 16 * 128; i += 256) {
        int r = i >> 7, k = i & 127;
        sH[i] = Hm[(size_t)(row0 + r) * 128 + k];
    }
    __syncthreads();
    int r = t >> 4, c = t & 15;
    float acc = 0.f;
#pragma unroll 8
    for (int k = 0; k < 128; k++) acc = fmaf(sH[r * 128 + k], sW[k * 16 + c], acc);
    g_h2[(size_t)(row0 + r) * 16 + c] = acc;
}

// ---------------- 6: SpMM diffusion step, F=16 (16 lanes/row), final fuses log_softmax ----
template <bool FINAL>
__global__ void spmm_c(const float* __restrict__ in, const float* __restrict__ h,
                       float* __restrict__ out, const float* __restrict__ bias) {
    int sub = threadIdx.x >> 4;
    int f   = threadIdx.x & 15;
    int row = blockIdx.x * 16 + sub;
    size_t base = (size_t)row * CAP;
    int cnt = g_cnt[row];
    float acc = 0.f;
#pragma unroll 4
    for (int e = 0; e < cnt; e++) {
        int   c = __ldg(&g_cols[base + e]);
        float v = __ldg(&g_vals[base + e]);
        acc = fmaf(v, __ldg(&in[(size_t)c * NCLS + f]), acc);
    }
    float val = C_PROP * acc + C_RES * h[(size_t)row * NCLS + f];
    if (FINAL) {
        val += bias[f];
        float m = val;
#pragma unroll
        for (int s = 1; s < 16; s <<= 1)
            m = fmaxf(m, __shfl_xor_sync(0xffffffffu, m, s));
        float ex = expf(val - m);
        float ssum = ex;
#pragma unroll
        for (int s = 1; s < 16; s <<= 1)
            ssum += __shfl_xor_sync(0xffffffffu, ssum, s);
        val = val - m - logf(ssum);
    }
    out[(size_t)row * NCLS + f] = val;
}

// ---------------- launch ----------------
extern "C" void kernel_launch(void* const* d_in, const int* in_sizes, int n_in,
                              void* d_out, int out_size) {
    const float* x   = (const float*)d_in[0];
    const float* adj = (const float*)d_in[1];
    const float* W1  = (const float*)d_in[2];
    const float* b1  = (const float*)d_in[3];
    const float* W2  = (const float*)d_in[4];
    const float* b2  = (const float*)d_in[5];
    float* out = (float*)d_out;

    void *ph1, *pba, *pbb, *ph2, *pca, *pcb;
    cudaGetSymbolAddress(&ph1, g_h1);
    cudaGetSymbolAddress(&pba, g_b1a);
    cudaGetSymbolAddress(&pbb, g_b1b);
    cudaGetSymbolAddress(&ph2, g_h2);
    cudaGetSymbolAddress(&pca, g_c2a);
    cudaGetSymbolAddress(&pcb, g_c2b);
    float* h1 = (float*)ph1;
    float* ba = (float*)pba;
    float* bb = (float*)pbb;
    float* h2 = (float*)ph2;
    float* ca = (float*)pca;
    float* cb = (float*)pcb;

    // build normalized sparse adjacency
    deg_kernel<<<N_NODES, 256>>>(adj);
    build_kernel<<<N_NODES / 8, 256>>>(adj);

    // layer 1: h = x @ W1; 8 diffusion steps; final adds bias + relu
    gemm1_kernel<<<dim3(N_NODES / 64, HID / 64), 256>>>(x, W1, h1);
    spmm_h<false><<<N_NODES / 8, 256>>>(h1, h1, ba, b1);
    spmm_h<false><<<N_NODES / 8, 256>>>(ba, h1, bb, b1);
    spmm_h<false><<<N_NODES / 8, 256>>>(bb, h1, ba, b1);
    spmm_h<false><<<N_NODES / 8, 256>>>(ba, h1, bb, b1);
    spmm_h<false><<<N_NODES / 8, 256>>>(bb, h1, ba, b1);
    spmm_h<false><<<N_NODES / 8, 256>>>(ba, h1, bb, b1);
    spmm_h<false><<<N_NODES / 8, 256>>>(bb, h1, ba, b1);
    spmm_h<true ><<<N_NODES / 8, 256>>>(ba, h1, bb, b1);   // relu(out + b1) -> bb

    // layer 2: h2 = relu_out @ W2; 8 steps; final adds bias + log_softmax -> d_out
    gemm2_kernel<<<N_NODES / 16, 256>>>(bb, W2);
    spmm_c<false><<<N_NODES / 16, 256>>>(h2, h2, ca, b2);
    spmm_c<false><<<N_NODES / 16, 256>>>(ca, h2, cb, b2);
    spmm_c<false><<<N_NODES / 16, 256>>>(cb, h2, ca, b2);
    spmm_c<false><<<N_NODES / 16, 256>>>(ca, h2, cb, b2);
    spmm_c<false><<<N_NODES / 16, 256>>>(cb, h2, ca, b2);
    spmm_c<false><<<N_NODES / 16, 256>>>(ca, h2, cb, b2);
    spmm_c<false><<<N_NODES / 16, 256>>>(cb, h2, ca, b2);
    spmm_c<true ><<<N_NODES / 16, 256>>>(ca, h2, out, b2);
}

// round 2
// speedup vs baseline: 1.1151x; 1.1151x over previous
#include <cuda_runtime.h>
#include <cuda_fp16.h>
#include <math.h>

#define N_NODES 8192
#define F_IN    512
#define HID     128
#define NCLS    16
#define CAP     160

// ---------------- static scratch (no allocations allowed) ----------------
__device__ float  g_deg [N_NODES];
__device__ float  g_dinv[N_NODES];
__device__ int    g_cnt [N_NODES];
__device__ int    g_cols[(size_t)N_NODES * CAP];
__device__ float  g_vals[(size_t)N_NODES * CAP];
__device__ uint2  g_pack[(size_t)N_NODES * CAP];     // (col, val bits)
__device__ float  g_h1  [(size_t)N_NODES * HID];     // fp32 residual h
__device__ __half g_fa  [(size_t)N_NODES * HID];     // fp16 ping
__device__ __half g_fb  [(size_t)N_NODES * HID];     // fp16 pong
__device__ float  g_relu[(size_t)N_NODES * HID];     // layer-1 output (fp32)
__device__ float  g_h2  [(size_t)N_NODES * NCLS];
__device__ float  g_c2a [(size_t)N_NODES * NCLS];
__device__ float  g_c2b [(size_t)N_NODES * NCLS];

__device__ __constant__ float C_RES  = (float)(1.0 / 1.8);   // 1/(1+alpha)
__device__ __constant__ float C_PROP = (float)(0.8 / 1.8);   // alpha/(1+alpha)

// ---------------- 1: single-pass build: ELL + degree (one warp per row) ----------------
// Processes 128 columns / iteration (float4 per lane), software-pipelined 1 load ahead.
__global__ void build_kernel(const float* __restrict__ adj) {
    int warp = (blockIdx.x * blockDim.x + threadIdx.x) >> 5;
    int lane = threadIdx.x & 31;
    if (warp >= N_NODES) return;
    const int row = warp;
    const float4* rowp = (const float4*)(adj + (size_t)row * N_NODES);
    size_t base = (size_t)row * CAP;
    int cnt = 0;
    float s = 0.f;

    float4 v = __ldg(&rowp[lane]);
    for (int j0 = 0; j0 < N_NODES; j0 += 128) {
        float4 nv;
        if (j0 + 128 < N_NODES) nv = __ldg(&rowp[(j0 + 128) / 4 + lane]);
        int j = j0 + lane * 4;
        // self-loop
        v.x += (j + 0 == row) ? 1.f : 0.f;
        v.y += (j + 1 == row) ? 1.f : 0.f;
        v.z += (j + 2 == row) ? 1.f : 0.f;
        v.w += (j + 3 == row) ? 1.f : 0.f;
        s += v.x + v.y + v.z + v.w;
        int c = (v.x != 0.f) + (v.y != 0.f) + (v.z != 0.f) + (v.w != 0.f);
        // inclusive warp scan of c
        int incl = c;
#pragma unroll
        for (int d = 1; d < 32; d <<= 1) {
            int t = __shfl_up_sync(0xffffffffu, incl, d);
            if (lane >= d) incl += t;
        }
        int total = __shfl_sync(0xffffffffu, incl, 31);
        int w = cnt + incl - c;
        float vv[4] = {v.x, v.y, v.z, v.w};
#pragma unroll
        for (int q = 0; q < 4; q++) {
            if (vv[q] != 0.f) {
                if (w < CAP) { g_cols[base + w] = j + q; g_vals[base + w] = vv[q]; }
                w++;
            }
        }
        cnt += total;
        v = nv;
    }
#pragma unroll
    for (int d = 16; d; d >>= 1) s += __shfl_xor_sync(0xffffffffu, s, d);
    if (lane == 0) {
        g_cnt[row] = (cnt < CAP) ? cnt : CAP;
        g_deg[row] = s;
    }
}

// ---------------- 2: dinv ----------------
__global__ void dinv_kernel() {
    int i = blockIdx.x * blockDim.x + threadIdx.x;
    if (i < N_NODES) g_dinv[i] = rsqrtf(fmaxf(g_deg[i], 1e-12f));
}

// ---------------- 3: scale vals and pack (col,val) ----------------
__global__ void scale_kernel() {
    int warp = (blockIdx.x * blockDim.x + threadIdx.x) >> 5;
    int lane = threadIdx.x & 31;
    if (warp >= N_NODES) return;
    size_t base = (size_t)warp * CAP;
    int cnt = g_cnt[warp];
    float di = g_dinv[warp];
    for (int e = lane; e < cnt; e += 32) {
        int c = g_cols[base + e];
        float v = g_vals[base + e] * di * __ldg(&g_dinv[c]);
        g_pack[base + e] = make_uint2((unsigned)c, __float_as_uint(v));
    }
}

// ---------------- 4: SGEMM  C[8192,128] = A[8192,512] @ B[512,128], fp32 + fp16 out ----
__global__ void gemm1_kernel(const float* __restrict__ A, const float* __restrict__ B,
                             float* __restrict__ Cf, __half* __restrict__ Ch) {
    const int BM = 64, BN = 64, BK = 16;
    __shared__ float As[BK][BM];
    __shared__ float Bs[BK][BN];
    int m0 = blockIdx.x * BM;
    int n0 = blockIdx.y * BN;
    int t  = threadIdx.x;
    int tx = t & 15, ty = t >> 4;
    float acc[4][4] = {};
    for (int k0 = 0; k0 < F_IN; k0 += BK) {
        {
            int r = t >> 2, c4 = t & 3;
            float4 a = *(const float4*)(A + (size_t)(m0 + r) * F_IN + k0 + c4 * 4);
            As[c4 * 4 + 0][r] = a.x; As[c4 * 4 + 1][r] = a.y;
            As[c4 * 4 + 2][r] = a.z; As[c4 * 4 + 3][r] = a.w;
        }
        {
            int kr = t >> 4, c4 = t & 15;
            float4 b = *(const float4*)(B + (size_t)(k0 + kr) * HID + n0 + c4 * 4);
            Bs[kr][c4 * 4 + 0] = b.x; Bs[kr][c4 * 4 + 1] = b.y;
            Bs[kr][c4 * 4 + 2] = b.z; Bs[kr][c4 * 4 + 3] = b.w;
        }
        __syncthreads();
#pragma unroll
        for (int k = 0; k < BK; k++) {
            float av[4], bv[4];
#pragma unroll
            for (int i = 0; i < 4; i++) av[i] = As[k][ty * 4 + i];
#pragma unroll
            for (int j = 0; j < 4; j++) bv[j] = Bs[k][tx * 4 + j];
#pragma unroll
            for (int i = 0; i < 4; i++)
#pragma unroll
                for (int j = 0; j < 4; j++)
                    acc[i][j] = fmaf(av[i], bv[j], acc[i][j]);
        }
        __syncthreads();
    }
#pragma unroll
    for (int i = 0; i < 4; i++) {
        size_t off = (size_t)(m0 + ty * 4 + i) * HID + n0 + tx * 4;
        float4 r = make_float4(acc[i][0], acc[i][1], acc[i][2], acc[i][3]);
        *(float4*)(Cf + off) = r;
        __half2 h0 = __floats2half2_rn(r.x, r.y);
        __half2 h1 = __floats2half2_rn(r.z, r.w);
        *(uint2*)(Ch + off) = make_uint2(*(unsigned*)&h0, *(unsigned*)&h1);
    }
}

// ---------------- 5: SpMM diffusion step, F=128, fp16 gather / fp32 accum ----------------
template <bool FINAL>
__global__ void spmm_h16(const __half* __restrict__ in, const float* __restrict__ h,
                         __half* __restrict__ out, float* __restrict__ outf,
                         const float* __restrict__ bias) {
    int warp = threadIdx.x >> 5;
    int lane = threadIdx.x & 31;
    int row  = blockIdx.x * 8 + warp;
    size_t base = (size_t)row * CAP;
    int cnt = g_cnt[row];
    const uint2* __restrict__ ev  = g_pack + base;
    const uint2* __restrict__ inv = (const uint2*)in;     // 4 halves per lane
    float ax = 0.f, ay = 0.f, az = 0.f, aw = 0.f;
#pragma unroll 4
    for (int e = 0; e < cnt; e++) {
        uint2 p = __ldg(&ev[e]);
        int   c = (int)p.x;
        float v = __uint_as_float(p.y);
        uint2 o = __ldg(&inv[(size_t)c * 32 + lane]);
        float2 f0 = __half22float2(*(__half2*)&o.x);
        float2 f1 = __half22float2(*(__half2*)&o.y);
        ax = fmaf(v, f0.x, ax);
        ay = fmaf(v, f0.y, ay);
        az = fmaf(v, f1.x, az);
        aw = fmaf(v, f1.y, aw);
    }
    float4 hh = ((const float4*)h)[(size_t)row * 32 + lane];
    float4 r;
    r.x = C_PROP * ax + C_RES * hh.x;
    r.y = C_PROP * ay + C_RES * hh.y;
    r.z = C_PROP * az + C_RES * hh.z;
    r.w = C_PROP * aw + C_RES * hh.w;
    if (FINAL) {
        float4 b = ((const float4*)bias)[lane];
        r.x = fmaxf(r.x + b.x, 0.f);
        r.y = fmaxf(r.y + b.y, 0.f);
        r.z = fmaxf(r.z + b.z, 0.f);
        r.w = fmaxf(r.w + b.w, 0.f);
        ((float4*)outf)[(size_t)row * 32 + lane] = r;
    } else {
        __half2 h0 = __floats2half2_rn(r.x, r.y);
        __half2 h1 = __floats2half2_rn(r.z, r.w);
        ((uint2*)out)[(size_t)row * 32 + lane] = make_uint2(*(unsigned*)&h0, *(unsigned*)&h1);
    }
}

// ---------------- 6: small GEMM  h2[8192,16] = H[8192,128] @ W2[128,16] ----------------
__global__ void gemm2_kernel(const float* __restrict__ Hm, const float* __restrict__ W2) {
    __shared__ float sW[128 * 16];
    __shared__ float sH[16 * 128];
    int t = threadIdx.x;
    int row0 = blockIdx.x * 16;
    for (int i = t; i < 128 * 16; i += 256) sW[i] = W2[i];
    for (int i = t; i < 16 * 128; i += 256) {
        int r = i >> 7, k = i & 127;
        sH[i] = Hm[(size_t)(row0 + r) * 128 + k];
    }
    __syncthreads();
    int r = t >> 4, c = t & 15;
    float acc = 0.f;
#pragma unroll 8
    for (int k = 0; k < 128; k++) acc = fmaf(sH[r * 128 + k], sW[k * 16 + c], acc);
    g_h2[(size_t)(row0 + r) * 16 + c] = acc;
}

// ---------------- 7: SpMM diffusion step, F=16, fp32; final fuses log_softmax ----------
template <bool FINAL>
__global__ void spmm_c(const float* __restrict__ in, const float* __restrict__ h,
                       float* __restrict__ out, const float* __restrict__ bias) {
    int sub = threadIdx.x >> 4;
    int f   = threadIdx.x & 15;
    int row = blockIdx.x * 16 + sub;
    size_t base = (size_t)row * CAP;
    int cnt = g_cnt[row];
    const uint2* __restrict__ ev = g_pack + base;
    float acc = 0.f;
#pragma unroll 4
    for (int e = 0; e < cnt; e++) {
        uint2 p = __ldg(&ev[e]);
        int   c = (int)p.x;
        float v = __uint_as_float(p.y);
        acc = fmaf(v, __ldg(&in[(size_t)c * NCLS + f]), acc);
    }
    float val = C_PROP * acc + C_RES * h[(size_t)row * NCLS + f];
    if (FINAL) {
        val += bias[f];
        float m = val;
#pragma unroll
        for (int s = 1; s < 16; s <<= 1)
            m = fmaxf(m, __shfl_xor_sync(0xffffffffu, m, s));
        float ex = expf(val - m);
        float ssum = ex;
#pragma unroll
        for (int s = 1; s < 16; s <<= 1)
            ssum += __shfl_xor_sync(0xffffffffu, ssum, s);
        val = val - m - logf(ssum);
    }
    out[(size_t)row * NCLS + f] = val;
}

// ---------------- launch ----------------
extern "C" void kernel_launch(void* const* d_in, const int* in_sizes, int n_in,
                              void* d_out, int out_size) {
    const float* x   = (const float*)d_in[0];
    const float* adj = (const float*)d_in[1];
    const float* W1  = (const float*)d_in[2];
    const float* b1  = (const float*)d_in[3];
    const float* W2  = (const float*)d_in[4];
    const float* b2  = (const float*)d_in[5];
    float* out = (float*)d_out;

    void *ph1, *pfa, *pfb, *prl, *ph2, *pca, *pcb;
    cudaGetSymbolAddress(&ph1, g_h1);
    cudaGetSymbolAddress(&pfa, g_fa);
    cudaGetSymbolAddress(&pfb, g_fb);
    cudaGetSymbolAddress(&prl, g_relu);
    cudaGetSymbolAddress(&ph2, g_h2);
    cudaGetSymbolAddress(&pca, g_c2a);
    cudaGetSymbolAddress(&pcb, g_c2b);
    float*  h1 = (float*)ph1;
    __half* fa = (__half*)pfa;
    __half* fb = (__half*)pfb;
    float*  rl = (float*)prl;
    float*  h2 = (float*)ph2;
    float*  ca = (float*)pca;
    float*  cb = (float*)pcb;

    // build normalized sparse adjacency (single pass over adj)
    build_kernel<<<N_NODES / 8, 256>>>(adj);
    dinv_kernel<<<N_NODES / 256, 256>>>();
    scale_kernel<<<N_NODES / 8, 256>>>();

    // layer 1: h = x @ W1 (fp32 + fp16 copies); 8 diffusion steps (fp16 gather)
    gemm1_kernel<<<dim3(N_NODES / 64, HID / 64), 256>>>(x, W1, h1, fa);
    spmm_h16<false><<<N_NODES / 8, 256>>>(fa, h1, fb, nullptr, b1);
    spmm_h16<false><<<N_NODES / 8, 256>>>(fb, h1, fa, nullptr, b1);
    spmm_h16<false><<<N_NODES / 8, 256>>>(fa, h1, fb, nullptr, b1);
    spmm_h16<false><<<N_NODES / 8, 256>>>(fb, h1, fa, nullptr, b1);
    spmm_h16<false><<<N_NODES / 8, 256>>>(fa, h1, fb, nullptr, b1);
    spmm_h16<false><<<N_NODES / 8, 256>>>(fb, h1, fa, nullptr, b1);
    spmm_h16<false><<<N_NODES / 8, 256>>>(fa, h1, fb, nullptr, b1);
    spmm_h16<true ><<<N_NODES / 8, 256>>>(fb, h1, nullptr, rl, b1);  // relu(out+b1) fp32

    // layer 2: h2 = relu_out @ W2; 8 steps fp32; final adds bias + log_softmax -> d_out
    gemm2_kernel<<<N_NODES / 16, 256>>>(rl, W2);
    spmm_c<false><<<N_NODES / 16, 256>>>(h2, h2, ca, b2);
    spmm_c<false><<<N_NODES / 16, 256>>>(ca, h2, cb, b2);
    spmm_c<false><<<N_NODES / 16, 256>>>(cb, h2, ca, b2);
    spmm_c<false><<<N_NODES / 16, 256>>>(ca, h2, cb, b2);
    spmm_c<false><<<N_NODES / 16, 256>>>(cb, h2, ca, b2);
    spmm_c<false><<<N_NODES / 16, 256>>>(ca, h2, cb, b2);
    spmm_c<false><<<N_NODES / 16, 256>>>(cb, h2, ca, b2);
    spmm_c<true ><<<N_NODES / 16, 256>>>(ca, h2, out, b2);
}

// round 5
// speedup vs baseline: 1.1242x; 1.0081x over previous
#include <cuda_runtime.h>
#include <cuda_fp16.h>
#include <math.h>

#define N_NODES 8192
#define F_IN    512
#define HID     128
#define NCLS    16
#define CAP     160
#define KSPLIT  4

// ---------------- static scratch (no allocations allowed) ----------------
__device__ float  g_deg [N_NODES];
__device__ float  g_dinv[N_NODES];
__device__ int    g_cnt [N_NODES];
__device__ int    g_cols[(size_t)N_NODES * CAP];
__device__ float  g_vals[(size_t)N_NODES * CAP];
__device__ uint2  g_pack[(size_t)N_NODES * CAP];          // (col, val bits)
__device__ float  g_part[(size_t)KSPLIT * N_NODES * HID]; // split-K partials
__device__ float  g_h1  [(size_t)N_NODES * HID];          // fp32 residual h
__device__ __half g_fa  [(size_t)N_NODES * HID];          // fp16 ping
__device__ __half g_fb  [(size_t)N_NODES * HID];          // fp16 pong
__device__ float  g_relu[(size_t)N_NODES * HID];          // layer-1 output fp32
__device__ float  g_h2  [(size_t)N_NODES * NCLS];         // fp32 residual h2
__device__ __half g_ca  [(size_t)N_NODES * NCLS];         // fp16 ping (layer2)
__device__ __half g_cb  [(size_t)N_NODES * NCLS];         // fp16 pong (layer2)

__device__ __constant__ float C_RES  = (float)(1.0 / 1.8);   // 1/(1+alpha)
__device__ __constant__ float C_PROP = (float)(0.8 / 1.8);   // alpha/(1+alpha)

// ---------------- 1: single-pass build: ELL + degree (one warp per row) ----------------
__global__ void build_kernel(const float* __restrict__ adj) {
    int warp = (blockIdx.x * blockDim.x + threadIdx.x) >> 5;
    int lane = threadIdx.x & 31;
    if (warp >= N_NODES) return;
    const int row = warp;
    const float4* rowp = (const float4*)(adj + (size_t)row * N_NODES);
    size_t base = (size_t)row * CAP;
    int cnt = 0;
    float s = 0.f;

    float4 v = __ldg(&rowp[lane]);
    for (int j0 = 0; j0 < N_NODES; j0 += 128) {
        float4 nv;
        if (j0 + 128 < N_NODES) nv = __ldg(&rowp[(j0 + 128) / 4 + lane]);
        int j = j0 + lane * 4;
        v.x += (j + 0 == row) ? 1.f : 0.f;
        v.y += (j + 1 == row) ? 1.f : 0.f;
        v.z += (j + 2 == row) ? 1.f : 0.f;
        v.w += (j + 3 == row) ? 1.f : 0.f;
        s += v.x + v.y + v.z + v.w;
        int c = (v.x != 0.f) + (v.y != 0.f) + (v.z != 0.f) + (v.w != 0.f);
        int incl = c;
#pragma unroll
        for (int d = 1; d < 32; d <<= 1) {
            int t = __shfl_up_sync(0xffffffffu, incl, d);
            if (lane >= d) incl += t;
        }
        int total = __shfl_sync(0xffffffffu, incl, 31);
        int w = cnt + incl - c;
        float vv[4] = {v.x, v.y, v.z, v.w};
#pragma unroll
        for (int q = 0; q < 4; q++) {
            if (vv[q] != 0.f) {
                if (w < CAP) { g_cols[base + w] = j + q; g_vals[base + w] = vv[q]; }
                w++;
            }
        }
        cnt += total;
        v = nv;
    }
#pragma unroll
    for (int d = 16; d; d >>= 1) s += __shfl_xor_sync(0xffffffffu, s, d);
    if (lane == 0) {
        g_cnt[row] = (cnt < CAP) ? cnt : CAP;
        g_deg[row] = s;
    }
}

// ---------------- 2: dinv ----------------
__global__ void dinv_kernel() {
    int i = blockIdx.x * blockDim.x + threadIdx.x;
    if (i < N_NODES) g_dinv[i] = rsqrtf(fmaxf(g_deg[i], 1e-12f));
}

// ---------------- 3: scale vals and pack (col,val) ----------------
__global__ void scale_kernel() {
    int warp = (blockIdx.x * blockDim.x + threadIdx.x) >> 5;
    int lane = threadIdx.x & 31;
    if (warp >= N_NODES) return;
    size_t base = (size_t)warp * CAP;
    int cnt = g_cnt[warp];
    float di = g_dinv[warp];
    for (int e = lane; e < cnt; e += 32) {
        int c = g_cols[base + e];
        float v = g_vals[base + e] * di * __ldg(&g_dinv[c]);
        g_pack[base + e] = make_uint2((unsigned)c, __float_as_uint(v));
    }
}

// ---------------- 4: split-K SGEMM  part[z] = A[:, zK:(z+1)K] @ B[zK:(z+1)K, :] ------
__global__ void gemm1_kernel(const float* __restrict__ A, const float* __restrict__ B) {
    const int BM = 64, BN = 64, BK = 16, KC = F_IN / KSPLIT;  // 128
    __shared__ float As[BK][BM];
    __shared__ float Bs[BK][BN];
    int m0 = blockIdx.x * BM;
    int n0 = blockIdx.y * BN;
    int kz = blockIdx.z;
    float* P = g_part + (size_t)kz * N_NODES * HID;
    int t  = threadIdx.x;
    int tx = t & 15, ty = t >> 4;
    float acc[4][4] = {};
    for (int k0 = kz * KC; k0 < kz * KC + KC; k0 += BK) {
        {
            int r = t >> 2, c4 = t & 3;
            float4 a = *(const float4*)(A + (size_t)(m0 + r) * F_IN + k0 + c4 * 4);
            As[c4 * 4 + 0][r] = a.x; As[c4 * 4 + 1][r] = a.y;
            As[c4 * 4 + 2][r] = a.z; As[c4 * 4 + 3][r] = a.w;
        }
        {
            int kr = t >> 4, c4 = t & 15;
            float4 b = *(const float4*)(B + (size_t)(k0 + kr) * HID + n0 + c4 * 4);
            Bs[kr][c4 * 4 + 0] = b.x; Bs[kr][c4 * 4 + 1] = b.y;
            Bs[kr][c4 * 4 + 2] = b.z; Bs[kr][c4 * 4 + 3] = b.w;
        }
        __syncthreads();
#pragma unroll
        for (int k = 0; k < BK; k++) {
            float av[4], bv[4];
#pragma unroll
            for (int i = 0; i < 4; i++) av[i] = As[k][ty * 4 + i];
#pragma unroll
            for (int j = 0; j < 4; j++) bv[j] = Bs[k][tx * 4 + j];
#pragma unroll
            for (int i = 0; i < 4; i++)
#pragma unroll
                for (int j = 0; j < 4; j++)
                    acc[i][j] = fmaf(av[i], bv[j], acc[i][j]);
        }
        __syncthreads();
    }
#pragma unroll
    for (int i = 0; i < 4; i++) {
        size_t off = (size_t)(m0 + ty * 4 + i) * HID + n0 + tx * 4;
        *(float4*)(P + off) = make_float4(acc[i][0], acc[i][1], acc[i][2], acc[i][3]);
    }
}

// ---------------- 4b: reduce split-K partials -> fp32 h1 + fp16 fa ----------------
__global__ void reduce_kernel() {
    size_t i = (size_t)(blockIdx.x * blockDim.x + threadIdx.x);   // float4 index
    const size_t TOT = (size_t)N_NODES * HID / 4;
    if (i >= TOT) return;
    const float4* p0 = (const float4*)g_part;
    float4 a = p0[i];
    float4 b = p0[TOT + i];
    float4 c = p0[2 * TOT + i];
    float4 d = p0[3 * TOT + i];
    float4 r;
    r.x = (a.x + b.x) + (c.x + d.x);
    r.y = (a.y + b.y) + (c.y + d.y);
    r.z = (a.z + b.z) + (c.z + d.z);
    r.w = (a.w + b.w) + (c.w + d.w);
    ((float4*)g_h1)[i] = r;
    __half2 h0 = __floats2half2_rn(r.x, r.y);
    __half2 h1 = __floats2half2_rn(r.z, r.w);
    ((uint2*)g_fa)[i] = make_uint2(*(unsigned*)&h0, *(unsigned*)&h1);
}

// ---------------- 5: SpMM diffusion step, F=128, fp16 gather / fp32 accum --------------
template <bool FINAL>
__global__ void spmm_h16(const __half* __restrict__ in, const float* __restrict__ h,
                         __half* __restrict__ out, float* __restrict__ outf,
                         const float* __restrict__ bias) {
    int warp = threadIdx.x >> 5;
    int lane = threadIdx.x & 31;
    int row  = blockIdx.x * 8 + warp;
    size_t base = (size_t)row * CAP;
    int cnt = g_cnt[row];
    const uint2* __restrict__ ev  = g_pack + base;
    const uint2* __restrict__ inv = (const uint2*)in;
    float ax = 0.f, ay = 0.f, az = 0.f, aw = 0.f;
#pragma unroll 4
    for (int e = 0; e < cnt; e++) {
        uint2 p = __ldg(&ev[e]);
        int   c = (int)p.x;
        float v = __uint_as_float(p.y);
        uint2 o = __ldg(&inv[(size_t)c * 32 + lane]);
        float2 f0 = __half22float2(*(__half2*)&o.x);
        float2 f1 = __half22float2(*(__half2*)&o.y);
        ax = fmaf(v, f0.x, ax);
        ay = fmaf(v, f0.y, ay);
        az = fmaf(v, f1.x, az);
        aw = fmaf(v, f1.y, aw);
    }
    float4 hh = ((const float4*)h)[(size_t)row * 32 + lane];
    float4 r;
    r.x = C_PROP * ax + C_RES * hh.x;
    r.y = C_PROP * ay + C_RES * hh.y;
    r.z = C_PROP * az + C_RES * hh.z;
    r.w = C_PROP * aw + C_RES * hh.w;
    if (FINAL) {
        float4 b = ((const float4*)bias)[lane];
        r.x = fmaxf(r.x + b.x, 0.f);
        r.y = fmaxf(r.y + b.y, 0.f);
        r.z = fmaxf(r.z + b.z, 0.f);
        r.w = fmaxf(r.w + b.w, 0.f);
        ((float4*)outf)[(size_t)row * 32 + lane] = r;
    } else {
        __half2 h0 = __floats2half2_rn(r.x, r.y);
        __half2 h1 = __floats2half2_rn(r.z, r.w);
        ((uint2*)out)[(size_t)row * 32 + lane] = make_uint2(*(unsigned*)&h0, *(unsigned*)&h1);
    }
}

// ---------------- 6: small GEMM  h2 = H @ W2 (fp32 residual + fp16 copy) --------------
__global__ void gemm2_kernel(const float* __restrict__ Hm, const float* __restrict__ W2) {
    __shared__ float sW[128 * 16];
    __shared__ float sH[16 * 128];
    int t = threadIdx.x;
    int row0 = blockIdx.x * 16;
    for (int i = t; i < 128 * 16; i += 256) sW[i] = W2[i];
    for (int i = t; i < 16 * 128; i += 256) {
        int r = i >> 7, k = i & 127;
        sH[i] = Hm[(size_t)(row0 + r) * 128 + k];
    }
    __syncthreads();
    int r = t >> 4, c = t & 15;
    float acc = 0.f;
#pragma unroll 8
    for (int k = 0; k < 128; k++) acc = fmaf(sH[r * 128 + k], sW[k * 16 + c], acc);
    size_t off = (size_t)(row0 + r) * 16 + c;
    g_h2[off] = acc;
    g_ca[off] = __float2half_rn(acc);
}

// ---------------- 7: SpMM diffusion step, F=16 fp16 gather (8 lanes/row, half2) -------
template <bool FINAL>
__global__ void spmm_c16(const __half* __restrict__ in, const float* __restrict__ h,
                         __half* __restrict__ out, float* __restrict__ outf,
                         const float* __restrict__ bias) {
    int sub  = threadIdx.x >> 3;          // row within block (32 rows/block)
    int lane = threadIdx.x & 7;           // 8 lanes per row, half2 each
    int row  = blockIdx.x * 32 + sub;
    size_t base = (size_t)row * CAP;
    int cnt = g_cnt[row];
    const uint2* __restrict__ ev = g_pack + base;
    const unsigned* __restrict__ inv = (const unsigned*)in;   // half2 per lane
    float a0 = 0.f, a1 = 0.f;
#pragma unroll 4
    for (int e = 0; e < cnt; e++) {
        uint2 p = __ldg(&ev[e]);
        int   c = (int)p.x;
        float v = __uint_as_float(p.y);
        unsigned o = __ldg(&inv[(size_t)c * 8 + lane]);
        float2 f = __half22float2(*(__half2*)&o);
        a0 = fmaf(v, f.x, a0);
        a1 = fmaf(v, f.y, a1);
    }
    float2 hh = ((const float2*)h)[(size_t)row * 8 + lane];
    float r0 = C_PROP * a0 + C_RES * hh.x;
    float r1 = C_PROP * a1 + C_RES * hh.y;
    if (FINAL) {
        float2 b = ((const float2*)bias)[lane];
        r0 += b.x;
        r1 += b.y;
        float m = fmaxf(r0, r1);
#pragma unroll
        for (int s = 1; s < 8; s <<= 1)
            m = fmaxf(m, __shfl_xor_sync(0xffffffffu, m, s, 8));
        float ssum = expf(r0 - m) + expf(r1 - m);
#pragma unroll
        for (int s = 1; s < 8; s <<= 1)
            ssum += __shfl_xor_sync(0xffffffffu, ssum, s, 8);
        float lse = m + logf(ssum);
        r0 -= lse;
        r1 -= lse;
        ((float2*)outf)[(size_t)row * 8 + lane] = make_float2(r0, r1);
    } else {
        __half2 hv = __floats2half2_rn(r0, r1);
        ((unsigned*)out)[(size_t)row * 8 + lane] = *(unsigned*)&hv;
    }
}

// ---------------- launch ----------------
extern "C" void kernel_launch(void* const* d_in, const int* in_sizes, int n_in,
                              void* d_out, int out_size) {
    const float* x   = (const float*)d_in[0];
    const float* adj = (const float*)d_in[1];
    const float* W1  = (const float*)d_in[2];
    const float* b1  = (const float*)d_in[3];
    const float* W2  = (const float*)d_in[4];
    const float* b2  = (const float*)d_in[5];
    float* out = (float*)d_out;

    void *ph1, *pfa, *pfb, *prl, *ph2, *pca, *pcb;
    cudaGetSymbolAddress(&ph1, g_h1);
    cudaGetSymbolAddress(&pfa, g_fa);
    cudaGetSymbolAddress(&pfb, g_fb);
    cudaGetSymbolAddress(&prl, g_relu);
    cudaGetSymbolAddress(&ph2, g_h2);
    cudaGetSymbolAddress(&pca, g_ca);
    cudaGetSymbolAddress(&pcb, g_cb);
    float*  h1 = (float*)ph1;
    __half* fa = (__half*)pfa;
    __half* fb = (__half*)pfb;
    float*  rl = (float*)prl;
    float*  h2 = (float*)ph2;
    __half* ca = (__half*)pca;
    __half* cb = (__half*)pcb;

    // build normalized sparse adjacency (single pass over adj)
    build_kernel<<<N_NODES / 8, 256>>>(adj);
    dinv_kernel<<<N_NODES / 256, 256>>>();
    scale_kernel<<<N_NODES / 8, 256>>>();

    // layer 1: h = x @ W1 via split-K; 8 diffusion steps (fp16 gather)
    gemm1_kernel<<<dim3(N_NODES / 64, HID / 64, KSPLIT), 256>>>(x, W1);
    reduce_kernel<<<N_NODES * HID / 4 / 256, 256>>>();
    spmm_h16<false><<<N_NODES / 8, 256>>>(fa, h1, fb, nullptr, b1);
    spmm_h16<false><<<N_NODES / 8, 256>>>(fb, h1, fa, nullptr, b1);
    spmm_h16<false><<<N_NODES / 8, 256>>>(fa, h1, fb, nullptr, b1);
    spmm_h16<false><<<N_NODES / 8, 256>>>(fb, h1, fa, nullptr, b1);
    spmm_h16<false><<<N_NODES / 8, 256>>>(fa, h1, fb, nullptr, b1);
    spmm_h16<false><<<N_NODES / 8, 256>>>(fb, h1, fa, nullptr, b1);
    spmm_h16<false><<<N_NODES / 8, 256>>>(fa, h1, fb, nullptr, b1);
    spmm_h16<true ><<<N_NODES / 8, 256>>>(fb, h1, nullptr, rl, b1);  // relu(out+b1) fp32

    // layer 2: h2 = relu_out @ W2; 8 fp16 diffusion steps; final = bias + log_softmax
    gemm2_kernel<<<N_NODES / 16, 256>>>(rl, W2);
    spmm_c16<false><<<N_NODES / 32, 256>>>(ca, h2, cb, nullptr, b2);
    spmm_c16<false><<<N_NODES / 32, 256>>>(cb, h2, ca, nullptr, b2);
    spmm_c16<false><<<N_NODES / 32, 256>>>(ca, h2, cb, nullptr, b2);
    spmm_c16<false><<<N_NODES / 32, 256>>>(cb, h2, ca, nullptr, b2);
    spmm_c16<false><<<N_NODES / 32, 256>>>(ca, h2, cb, nullptr, b2);
    spmm_c16<false><<<N_NODES / 32, 256>>>(cb, h2, ca, nullptr, b2);
    spmm_c16<false><<<N_NODES / 32, 256>>>(ca, h2, cb, nullptr, b2);
    spmm_c16<true ><<<N_NODES / 32, 256>>>(cb, h2, nullptr, out, b2);
}